// round 2
// baseline (speedup 1.0000x reference)
#include <cuda_runtime.h>
#include <cuda_bf16.h>
#include <cstdint>

// Problem constants
#define NN   128            // state size
#define NB   2              // batch
#define LL   2048           // sequence length
#define TC   32             // chunk length
#define KC   (LL / TC)      // 64 chunks

// ---------------- device scratch (no allocations allowed) ----------------
__device__ double g_ATd[NN * NN];     // ATd[j*128+i] = A[i][j]  (fp64)
__device__ float  g_AdT[NN * NN];     // AdT[k*128+j] = Ad[j][k]
__device__ float  g_Bd[NN];
__device__ float  g_AdPT[NN * NN];    // (Ad^32) transposed: AdPT[k*128+j] = AdP[j][k]
__device__ float  g_locend[NB * KC * NN];  // local (zero-init) chunk end states
__device__ float  g_carry[NB * KC * NN];   // state entering each chunk

// ---------------- 1) transpose A to fp64 ----------------
__global__ void k_transpose(const float* __restrict__ A) {
    __shared__ float tile[32][33];
    int bx = blockIdx.x * 32, by = blockIdx.y * 32;
    int x = bx + threadIdx.x;
    for (int r = threadIdx.y; r < 32; r += 8)
        tile[r][threadIdx.x] = A[(by + r) * NN + x];
    __syncthreads();
    int xo = by + threadIdx.x;
    for (int r = threadIdx.y; r < 32; r += 8)
        g_ATd[(bx + r) * NN + xo] = (double)tile[threadIdx.x][r];
}

// ---------------- 2) discretize: forward substitution per column ----------------
// Solve (I - 0.5 A) X = (I + 0.5 A) columnwise, and (I - 0.5 A) Bd = B.
// A is lower triangular. Block c in [0,129): c<128 -> column c of Ad, c==128 -> Bd.
__global__ void __launch_bounds__(NN) k_disc(const float* __restrict__ A,
                                             const float* __restrict__ B) {
    __shared__ double xsh;
    int c = blockIdx.x, i = threadIdx.x;
    double ri;
    if (c < NN) ri = (i == c ? 1.0 : 0.0) + 0.5 * g_ATd[c * NN + i];
    else        ri = (double)B[i];
    for (int j = 0; j < NN; j++) {
        if (i == j) {
            double ajj = g_ATd[j * NN + j];
            xsh = ri / (1.0 - 0.5 * ajj);
        }
        __syncthreads();
        double x = xsh;
        if (i > j)       ri += 0.5 * g_ATd[j * NN + i] * x;
        else if (i == j) ri = x;
        __syncthreads();
    }
    if (c < NN) g_AdT[c * NN + i] = (float)ri;   // Ad[i][c] stored at AdT[c*128+i]
    else        g_Bd[i] = (float)ri;
}

// full 128-dot with Ad row in registers, state broadcast from shared as float4
__device__ __forceinline__ float dot128(const float* __restrict__ ad,
                                        const float* __restrict__ csh) {
    const float4* c4 = (const float4*)csh;
    float a0 = 0.f, a1 = 0.f, a2 = 0.f, a3 = 0.f;
#pragma unroll
    for (int k4 = 0; k4 < 32; k4++) {
        float4 cv = c4[k4];
        a0 = fmaf(ad[4 * k4 + 0], cv.x, a0);
        a1 = fmaf(ad[4 * k4 + 1], cv.y, a1);
        a2 = fmaf(ad[4 * k4 + 2], cv.z, a2);
        a3 = fmaf(ad[4 * k4 + 3], cv.w, a3);
    }
    return (a0 + a1) + (a2 + a3);
}

// ---------------- 3) chunk locals + Ad^32 columns (one kernel, depth 32) -------
// blocks 0..127  : (b, chunk) local end state from zero init driven by f
// blocks 128..255: column j0 of Ad^32 (recurrence on basis vector, f = 0)
__global__ void __launch_bounds__(NN) k_chain(const float* __restrict__ f) {
    __shared__ float csh[NN];
    int j = threadIdx.x;
    float ad[NN];
#pragma unroll
    for (int k = 0; k < NN; k++) ad[k] = g_AdT[k * NN + j];

    int blk = blockIdx.x;
    float acc;
    if (blk < 128) {
        int b = blk >> 6, ch = blk & 63;
        float bd = g_Bd[j];
        const float* fp = f + b * LL + ch * TC;
        acc = bd * fp[0];              // c_0 = Bd f_0 (zero init)
        csh[j] = acc;
        __syncthreads();
        for (int s = 1; s < TC; s++) {
            float d = dot128(ad, csh);
            acc = fmaf(bd, fp[s], d);
            __syncthreads();
            csh[j] = acc;
            __syncthreads();
        }
        g_locend[(b * KC + ch) * NN + j] = acc;
    } else {
        int j0 = blk - 128;
        csh[j] = (j == j0) ? 1.0f : 0.0f;
        acc = csh[j];
        __syncthreads();
        for (int s = 0; s < TC; s++) {
            acc = dot128(ad, csh);
            __syncthreads();
            csh[j] = acc;
            __syncthreads();
        }
        g_AdPT[j0 * NN + j] = acc;     // column j0 -> transposed layout
    }
}

// ---------------- 4) sequential carry scan over chunks (per batch) -------------
__global__ void __launch_bounds__(NN) k_carry() {
    __shared__ float csh[NN];
    int j = threadIdx.x, b = blockIdx.x;
    float ap[NN];
#pragma unroll
    for (int k = 0; k < NN; k++) ap[k] = g_AdPT[k * NN + j];

    g_carry[(b * KC + 0) * NN + j] = 0.f;
    csh[j] = 0.f;
    __syncthreads();
    for (int ch = 1; ch < KC; ch++) {
        float d = dot128(ap, csh);
        float nc = d + g_locend[(b * KC + ch - 1) * NN + j];
        __syncthreads();
        csh[j] = nc;
        __syncthreads();
        g_carry[(b * KC + ch) * NN + j] = nc;
    }
}

// ---------------- 5) final recurrence with true carry + stream output ----------
// grid (64, 2), 256 threads: threads split the 128-dot in half (h = tid>>7),
// 32 states buffered in shared, then 2 MB of replicated output streamed per block.
__global__ void __launch_bounds__(256) k_out(const float* __restrict__ f,
                                             const float* __restrict__ C,
                                             const float* __restrict__ D,
                                             float* __restrict__ y,
                                             float* __restrict__ cfin) {
    __shared__ float states[TC][NN];
    __shared__ float cur[NN];
    __shared__ float part[NN];
    __shared__ float Csh[NN];

    int tid = threadIdx.x;
    int ch = blockIdx.x, b = blockIdx.y;
    int j = tid & 127, h = tid >> 7;

    float ad[64];
#pragma unroll
    for (int k = 0; k < 64; k++) ad[k] = g_AdT[(h * 64 + k) * NN + j];
    float bd = (h == 0) ? g_Bd[j] : 0.f;

    if (tid < NN) {
        Csh[tid] = C[tid];
        cur[tid] = g_carry[(b * KC + ch) * NN + tid];
    }
    float Dv = D[0];
    const float* fp = f + b * LL + ch * TC;
    __syncthreads();

    for (int s = 0; s < TC; s++) {
        float ft = fp[s];
        const float4* c4 = (const float4*)cur + h * 16;
        float a0 = 0.f, a1 = 0.f, a2 = 0.f, a3 = 0.f;
#pragma unroll
        for (int k4 = 0; k4 < 16; k4++) {
            float4 cv = c4[k4];
            a0 = fmaf(ad[4 * k4 + 0], cv.x, a0);
            a1 = fmaf(ad[4 * k4 + 1], cv.y, a1);
            a2 = fmaf(ad[4 * k4 + 2], cv.z, a2);
            a3 = fmaf(ad[4 * k4 + 3], cv.w, a3);
        }
        float p = (a0 + a1) + (a2 + a3);
        if (h == 0) p = fmaf(bd, ft, p);
        if (h == 1) part[j] = p;
        __syncthreads();                 // part ready; all cur reads done
        if (h == 0) {
            float nc = p + part[j];
            states[s][j] = nc;
            cur[j] = nc;
        }
        __syncthreads();
    }

    // stream 32 * 64KB of replicated rows: y[b,t,n,k] = C[n]*c_t[k] + D*f_t
    size_t base = ((size_t)(b * LL + ch * TC)) * (NN * NN);
    for (int s = 0; s < TC; s++) {
        float df = Dv * fp[s];
        float4* out = (float4*)(y + base + (size_t)s * (NN * NN));
        const float4* c4 = (const float4*)states[s];
#pragma unroll
        for (int it = 0; it < 16; it++) {
            int qq = tid + 256 * it;     // 4096 float4 per (b,t) tile
            int n = qq >> 5;
            float4 cv = c4[qq & 31];
            float cn = Csh[n];
            float4 o;
            o.x = fmaf(cn, cv.x, df);
            o.y = fmaf(cn, cv.y, df);
            o.z = fmaf(cn, cv.z, df);
            o.w = fmaf(cn, cv.w, df);
            out[qq] = o;
        }
    }

    if (cfin != nullptr && ch == KC - 1 && tid < NN)
        cfin[b * NN + tid] = states[TC - 1][tid];
}

// ---------------- launcher (graph-capturable, no syncs, no allocs) -------------
extern "C" void kernel_launch(void* const* d_in, const int* in_sizes, int n_in,
                              void* d_out, int out_size) {
    const float* f = (const float*)d_in[0];
    const float* A = (const float*)d_in[1];
    const float* B = (const float*)d_in[2];
    const float* C = (const float*)d_in[3];
    const float* D = (const float*)d_in[4];

    const long long Y_ELEMS = (long long)NB * LL * NN * NN;   // 67,108,864
    long long off = (long long)out_size - Y_ELEMS;            // c_final prefix (if any)
    if (off < 0) off = 0;
    float* y    = (float*)d_out + off;
    float* cfin = (off >= NB * NN) ? (float*)d_out : nullptr;

    k_transpose<<<dim3(4, 4), dim3(32, 8)>>>(A);
    k_disc<<<NN + 1, NN>>>(A, B);
    k_chain<<<2 * NN, NN>>>(f);
    k_carry<<<NB, NN>>>();
    k_out<<<dim3(KC, NB), 256>>>(f, C, D, y, cfin);
}

// round 3
// speedup vs baseline: 1.4019x; 1.4019x over previous
#include <cuda_runtime.h>
#include <cuda_bf16.h>
#include <cstdint>

// Problem constants
#define NN   128            // state size
#define NB   2              // batch
#define LL   2048           // sequence length
#define TC   32             // chunk length
#define KC   (LL / TC)      // 64 chunks

// ---------------- device scratch (no allocations allowed) ----------------
__device__ double g_ATd[NN * NN];     // ATd[j*128+i] = A[i][j]  (fp64)
__device__ float  g_AdT[NN * NN];     // AdT[k*128+j] = Ad[j][k]
__device__ float  g_Bd[NN];
__device__ float  g_AdPT[NN * NN];    // (Ad^32) transposed: AdPT[k*128+j] = AdP[j][k]
__device__ float  g_locend[NB * KC * NN];  // local (zero-init) chunk end states
__device__ float  g_carry[NB * KC * NN];   // state entering each chunk
__device__ float  g_states[NB * LL * NN];  // all true states c_t (2 MB)

// ---------------- 1) transpose A to fp64 ----------------
__global__ void k_transpose(const float* __restrict__ A) {
    __shared__ float tile[32][33];
    int bx = blockIdx.x * 32, by = blockIdx.y * 32;
    int x = bx + threadIdx.x;
    for (int r = threadIdx.y; r < 32; r += 8)
        tile[r][threadIdx.x] = A[(by + r) * NN + x];
    __syncthreads();
    int xo = by + threadIdx.x;
    for (int r = threadIdx.y; r < 32; r += 8)
        g_ATd[(bx + r) * NN + xo] = (double)tile[threadIdx.x][r];
}

// ---------------- 2) discretize: forward substitution per column ----------------
// Solve (I - 0.5 A) X = (I + 0.5 A) columnwise, and (I - 0.5 A) Bd = B.
// A lower triangular. Per-step: precomputed reciprocal diag, prefetched column,
// double-buffered broadcast -> 1 bar per step.
__global__ void __launch_bounds__(NN) k_disc(const float* __restrict__ B) {
    __shared__ double dinv[NN];
    __shared__ double xsh[2];
    int c = blockIdx.x, i = threadIdx.x;

    dinv[i] = 1.0 / (1.0 - 0.5 * g_ATd[i * NN + i]);

    double ri;
    if (c < NN) ri = (i == c ? 1.0 : 0.0) + 0.5 * g_ATd[c * NN + i];
    else        ri = (double)B[i];

    double a_next = 0.5 * g_ATd[0 * NN + i];   // column 0, prefetched
    __syncthreads();

    for (int j = 0; j < NN; j++) {
        double aj = a_next;
        if (j + 1 < NN) a_next = 0.5 * g_ATd[(j + 1) * NN + i];
        if (i == j) xsh[j & 1] = ri * dinv[j];
        __syncthreads();
        double x = xsh[j & 1];
        if (i > j)       ri = fma(aj, x, ri);
        else if (i == j) ri = x;
        // next write targets the other buffer; no second bar needed
    }
    if (c < NN) g_AdT[c * NN + i] = (float)ri;   // Ad[i][c] at AdT[c*128+i]
    else        g_Bd[i] = (float)ri;
}

// full 128-dot with Ad row in registers, state broadcast from shared as float4
__device__ __forceinline__ float dot128(const float* __restrict__ ad,
                                        const float* __restrict__ csh) {
    const float4* c4 = (const float4*)csh;
    float a0 = 0.f, a1 = 0.f, a2 = 0.f, a3 = 0.f;
#pragma unroll
    for (int k4 = 0; k4 < 32; k4++) {
        float4 cv = c4[k4];
        a0 = fmaf(ad[4 * k4 + 0], cv.x, a0);
        a1 = fmaf(ad[4 * k4 + 1], cv.y, a1);
        a2 = fmaf(ad[4 * k4 + 2], cv.z, a2);
        a3 = fmaf(ad[4 * k4 + 3], cv.w, a3);
    }
    return (a0 + a1) + (a2 + a3);
}

// ---------------- 3) chunk locals + Ad^32 columns (one kernel, depth 32) -------
// blocks 0..127  : (b, chunk) local end state from zero init driven by f
// blocks 128..255: column j0 of Ad^32 (recurrence on basis vector, f = 0)
__global__ void __launch_bounds__(NN) k_chain(const float* __restrict__ f) {
    __shared__ float csh[NN];
    int j = threadIdx.x;
    float ad[NN];
#pragma unroll
    for (int k = 0; k < NN; k++) ad[k] = g_AdT[k * NN + j];

    int blk = blockIdx.x;
    float acc;
    if (blk < 128) {
        int b = blk >> 6, ch = blk & 63;
        float bd = g_Bd[j];
        const float* fp = f + b * LL + ch * TC;
        acc = bd * fp[0];              // c_0 = Bd f_0 (zero init)
        csh[j] = acc;
        __syncthreads();
        for (int s = 1; s < TC; s++) {
            float d = dot128(ad, csh);
            acc = fmaf(bd, fp[s], d);
            __syncthreads();
            csh[j] = acc;
            __syncthreads();
        }
        g_locend[(b * KC + ch) * NN + j] = acc;
    } else {
        int j0 = blk - 128;
        csh[j] = (j == j0) ? 1.0f : 0.0f;
        acc = csh[j];
        __syncthreads();
        for (int s = 0; s < TC; s++) {
            acc = dot128(ad, csh);
            __syncthreads();
            csh[j] = acc;
            __syncthreads();
        }
        g_AdPT[j0 * NN + j] = acc;     // column j0 -> transposed layout
    }
}

// ---------------- 4) sequential carry scan (per batch), latency-optimized ------
// 512 threads: tid = j*4 + p. Each thread covers 32 k-values of the dot,
// reduced via 2x shfl.bfly. locend fully preloaded to shared. 1 bar/step.
// Also emits c_final (= carry after chunk KC).
__global__ void __launch_bounds__(512) k_carry(float* __restrict__ cfin) {
    __shared__ float le[KC][NN];       // 32 KB
    __shared__ float cur[2][NN];

    int tid = threadIdx.x, b = blockIdx.x;
    int j = tid >> 2, p = tid & 3;

    float ap[32];
#pragma unroll
    for (int k = 0; k < 32; k++) ap[k] = g_AdPT[(p * 32 + k) * NN + j];

    for (int idx = tid; idx < KC * NN; idx += 512)
        ((float*)le)[idx] = g_locend[b * KC * NN + idx];
    if (tid < NN) {
        cur[0][tid] = 0.f;
        g_carry[(b * KC + 0) * NN + tid] = 0.f;
    }
    __syncthreads();

    for (int ch = 1; ch <= KC; ch++) {
        int rb = (ch - 1) & 1, wb = ch & 1;
        const float4* c4 = (const float4*)&cur[rb][p * 32];
        float a0 = 0.f, a1 = 0.f, a2 = 0.f, a3 = 0.f;
#pragma unroll
        for (int k4 = 0; k4 < 8; k4++) {
            float4 cv = c4[k4];
            a0 = fmaf(ap[4 * k4 + 0], cv.x, a0);
            a1 = fmaf(ap[4 * k4 + 1], cv.y, a1);
            a2 = fmaf(ap[4 * k4 + 2], cv.z, a2);
            a3 = fmaf(ap[4 * k4 + 3], cv.w, a3);
        }
        float s = (a0 + a1) + (a2 + a3);
        s += __shfl_xor_sync(0xffffffffu, s, 1);
        s += __shfl_xor_sync(0xffffffffu, s, 2);
        if (p == 0) {
            float nc = s + le[ch - 1][j];
            if (ch < KC) {
                cur[wb][j] = nc;
                g_carry[(b * KC + ch) * NN + j] = nc;
            } else if (cfin != nullptr) {
                cfin[b * NN + j] = nc;     // c_final
            }
        }
        __syncthreads();
    }
}

// ---------------- 5) replay recurrence with true carry, store all states -------
// grid (64, 2), 256 threads: split the 128-dot in half (h = tid>>7).
__global__ void __launch_bounds__(256) k_states(const float* __restrict__ f) {
    __shared__ float cur[NN];
    __shared__ float part[NN];

    int tid = threadIdx.x;
    int ch = blockIdx.x, b = blockIdx.y;
    int j = tid & 127, h = tid >> 7;

    float ad[64];
#pragma unroll
    for (int k = 0; k < 64; k++) ad[k] = g_AdT[(h * 64 + k) * NN + j];
    float bd = (h == 0) ? g_Bd[j] : 0.f;

    if (tid < NN) cur[tid] = g_carry[(b * KC + ch) * NN + tid];
    const float* fp = f + b * LL + ch * TC;
    float* sp = g_states + ((size_t)(b * LL + ch * TC)) * NN;
    __syncthreads();

    for (int s = 0; s < TC; s++) {
        float ft = fp[s];
        const float4* c4 = (const float4*)cur + h * 16;
        float a0 = 0.f, a1 = 0.f, a2 = 0.f, a3 = 0.f;
#pragma unroll
        for (int k4 = 0; k4 < 16; k4++) {
            float4 cv = c4[k4];
            a0 = fmaf(ad[4 * k4 + 0], cv.x, a0);
            a1 = fmaf(ad[4 * k4 + 1], cv.y, a1);
            a2 = fmaf(ad[4 * k4 + 2], cv.z, a2);
            a3 = fmaf(ad[4 * k4 + 3], cv.w, a3);
        }
        float pt = (a0 + a1) + (a2 + a3);
        if (h == 0) pt = fmaf(bd, ft, pt);
        if (h == 1) part[j] = pt;
        __syncthreads();
        if (h == 0) {
            float nc = pt + part[j];
            cur[j] = nc;
            sp[(size_t)s * NN + j] = nc;   // async store, not on critical path
        }
        __syncthreads();
    }
}

// ---------------- 6) pure streaming expansion: y[b,t,n,k] = C[n]*c_t[k] + D*f_t
// grid (2048, 2), 256 threads; each block writes one 64 KB tile, coalesced.
__global__ void __launch_bounds__(256) k_expand(const float* __restrict__ f,
                                                const float* __restrict__ C,
                                                const float* __restrict__ D,
                                                float* __restrict__ y) {
    __shared__ float cs[NN];
    __shared__ float Csh[NN];
    int tid = threadIdx.x;
    int t = blockIdx.x, b = blockIdx.y;

    if (tid < NN) {
        cs[tid]  = g_states[((size_t)(b * LL + t)) * NN + tid];
        Csh[tid] = C[tid];
    }
    float df = D[0] * f[b * LL + t];
    __syncthreads();

    float4* out = (float4*)(y + ((size_t)(b * LL + t)) * (NN * NN));
    float4 cv = ((const float4*)cs)[tid & 31];
    int n0 = tid >> 5;
#pragma unroll
    for (int it = 0; it < 16; it++) {
        float cn = Csh[n0 + 8 * it];
        float4 o;
        o.x = fmaf(cn, cv.x, df);
        o.y = fmaf(cn, cv.y, df);
        o.z = fmaf(cn, cv.z, df);
        o.w = fmaf(cn, cv.w, df);
        out[tid + 256 * it] = o;
    }
}

// ---------------- launcher (graph-capturable, no syncs, no allocs) -------------
extern "C" void kernel_launch(void* const* d_in, const int* in_sizes, int n_in,
                              void* d_out, int out_size) {
    const float* f = (const float*)d_in[0];
    const float* A = (const float*)d_in[1];
    const float* B = (const float*)d_in[2];
    const float* C = (const float*)d_in[3];
    const float* D = (const float*)d_in[4];

    const long long Y_ELEMS = (long long)NB * LL * NN * NN;   // 67,108,864
    long long off = (long long)out_size - Y_ELEMS;            // c_final prefix (if any)
    if (off < 0) off = 0;
    float* y    = (float*)d_out + off;
    float* cfin = (off >= NB * NN) ? (float*)d_out : nullptr;

    k_transpose<<<dim3(4, 4), dim3(32, 8)>>>(A);
    k_disc<<<NN + 1, NN>>>(B);
    k_chain<<<2 * NN, NN>>>(f);
    k_carry<<<NB, 512>>>(cfin);
    k_states<<<dim3(KC, NB), 256>>>(f);
    k_expand<<<dim3(LL, NB), 256>>>(f, C, D, y);
}